// round 5
// baseline (speedup 1.0000x reference)
#include <cuda_runtime.h>
#include <math.h>

// Problem constants
#define BB 4
#define TT 2048
#define CC 1024
#define HH 16
#define HD 64
#define M_ROWS (BB * TT)       // 8192
#define N3 (3 * CC)            // 3072

// Scratch (device globals -- allocation API is forbidden)
__device__ float g_qkv[(size_t)M_ROWS * N3];     // 100.7 MB
__device__ float g_attn[(size_t)M_ROWS * CC];    // 33.6 MB

// ---------------------------------------------------------------------------
// Helpers
// ---------------------------------------------------------------------------
__device__ __forceinline__ unsigned f2tf32(float x) {
    unsigned r;
    asm("cvt.rna.tf32.f32 %0, %1;" : "=r"(r) : "f"(x));
    return r;
}
__device__ __forceinline__ float ex2f(float x) {
    float r;
    asm("ex2.approx.ftz.f32 %0, %1;" : "=f"(r) : "f"(x));
    return r;
}
__device__ __forceinline__ void mma_tf32(float* d, const unsigned* a, const unsigned* b) {
    asm volatile(
        "mma.sync.aligned.m16n8k8.row.col.f32.tf32.tf32.f32 "
        "{%0,%1,%2,%3}, {%4,%5,%6,%7}, {%8,%9}, {%0,%1,%2,%3};"
        : "+f"(d[0]), "+f"(d[1]), "+f"(d[2]), "+f"(d[3])
        : "r"(a[0]), "r"(a[1]), "r"(a[2]), "r"(a[3]), "r"(b[0]), "r"(b[1]));
}

extern __shared__ unsigned dynsm_u[];

// Permute within a 32-wide k block: pk(k) = (k%4)*8 + k/4.
// Fragment pair (k = ks*8+tig, k+4) lands at (pk, pk+1) -> one LDS.64.

// ---------------------------------------------------------------------------
// tf32 tensor GEMM. C[M,N] = A[M,K] @ B[K,N], row-major.
// CTA tile 256x128, BK=32, 256 threads, 8 warps (4 M x 2 N), warp tile 64x64.
// 3-stage smem, register-staged global loads, tf32 cvt at staging.
// A staged as A_perm[m][pk(k)] (stride 36); B staged TRANSPOSED as
// Bt[n][pk(k)] (stride 36). All fragment loads are conflict-free LDS.64.
// ---------------------------------------------------------------------------
#define GS 36
#define G_A_WORDS (256 * GS)          // 9216
#define G_B_WORDS (128 * GS)          // 4608
#define G_STG (G_A_WORDS + G_B_WORDS) // 13824
#define GEMM_SMEM_BYTES (3 * G_STG * 4)   // 165888

__global__ __launch_bounds__(256, 1)
void gemm_tf32(const float* __restrict__ A, const float* __restrict__ B,
               float* __restrict__ C, int M, int N, int K)
{
    const int tid  = threadIdx.x;
    const int lane = tid & 31;
    const int wid  = tid >> 5;
    const int gid  = lane >> 2;
    const int tig  = lane & 3;
    const int wm   = wid & 3;      // 0..3 -> M
    const int wn   = wid >> 2;     // 0..1 -> N
    const int bM   = blockIdx.y * 256;
    const int bN   = blockIdx.x * 128;

    float4 rA[8], rB[4];
    const int bk = tid & 31;                 // B staging row (k within tile)
    const int bn = (tid >> 5) * 16;          // B staging col base

    auto ldg = [&](int kb) {
        #pragma unroll
        for (int r = 0; r < 8; r++) {
            int idx = tid + r * 256;
            int row = idx >> 3;
            int c   = (idx & 7) * 4;
            rA[r] = *(const float4*)(A + (size_t)(bM + row) * K + kb + c);
        }
        #pragma unroll
        for (int r = 0; r < 4; r++) {
            rB[r] = *(const float4*)(B + (size_t)(kb + bk) * N + bN + bn + r * 4);
        }
    };
    auto sts = [&](int s) {
        unsigned* As = dynsm_u + s * G_STG;
        unsigned* Bt = As + G_A_WORDS;
        #pragma unroll
        for (int r = 0; r < 8; r++) {
            int idx = tid + r * 256;
            int row = idx >> 3;
            int c4  = idx & 7;               // c/4
            unsigned* p = As + row * GS + c4;
            p[0]  = f2tf32(rA[r].x);
            p[8]  = f2tf32(rA[r].y);
            p[16] = f2tf32(rA[r].z);
            p[24] = f2tf32(rA[r].w);
        }
        const int pk = (bk & 3) * 8 + (bk >> 2);
        #pragma unroll
        for (int r = 0; r < 4; r++) {
            unsigned* p = Bt + (bn + r * 4) * GS + pk;
            p[0 * GS] = f2tf32(rB[r].x);
            p[1 * GS] = f2tf32(rB[r].y);
            p[2 * GS] = f2tf32(rB[r].z);
            p[3 * GS] = f2tf32(rB[r].w);
        }
    };

    float acc[4][8][4];
    #pragma unroll
    for (int mi = 0; mi < 4; mi++)
        #pragma unroll
        for (int nj = 0; nj < 8; nj++)
            #pragma unroll
            for (int e = 0; e < 4; e++) acc[mi][nj][e] = 0.0f;

    const int ntile = K >> 5;
    // prologue: tile0 -> buf0, tile1 -> regs
    ldg(0);
    sts(0);
    if (ntile > 1) ldg(32);

    for (int i = 0; i < ntile; i++) {
        if (i + 1 < ntile) sts((i + 1) % 3);
        if (i + 2 < ntile) ldg((i + 2) * 32);
        __syncthreads();

        const unsigned* As = dynsm_u + (i % 3) * G_STG;
        const unsigned* Bt = As + G_A_WORDS;

        #pragma unroll
        for (int ks = 0; ks < 4; ks++) {
            const int off = tig * 8 + 2 * ks;
            uint2 qa[4][2];
            #pragma unroll
            for (int mi = 0; mi < 4; mi++) {
                int m = wm * 64 + mi * 16 + gid;
                qa[mi][0] = *(const uint2*)&As[m * GS + off];
                qa[mi][1] = *(const uint2*)&As[(m + 8) * GS + off];
            }
            #pragma unroll
            for (int nj = 0; nj < 8; nj++) {
                int n = wn * 64 + nj * 8 + gid;
                uint2 qb = *(const uint2*)&Bt[n * GS + off];
                unsigned bfr[2] = {qb.x, qb.y};
                #pragma unroll
                for (int mi = 0; mi < 4; mi++) {
                    unsigned afr[4] = {qa[mi][0].x, qa[mi][1].x, qa[mi][0].y, qa[mi][1].y};
                    mma_tf32(acc[mi][nj], afr, bfr);
                }
            }
        }
    }

    // Epilogue
    #pragma unroll
    for (int mi = 0; mi < 4; mi++) {
        #pragma unroll
        for (int nj = 0; nj < 8; nj++) {
            int row = bM + wm * 64 + mi * 16 + gid;
            int col = bN + wn * 64 + nj * 8 + 2 * tig;
            *(float2*)(C + (size_t)row * N + col) =
                make_float2(acc[mi][nj][0], acc[mi][nj][1]);
            *(float2*)(C + (size_t)(row + 8) * N + col) =
                make_float2(acc[mi][nj][2], acc[mi][nj][3]);
        }
    }
}

// ---------------------------------------------------------------------------
// Tensor-core flash attention (causal, tf32 mma, fp32 accum).
// CTA: 128 query rows, 4 warps x 32 rows. 64-key tiles, single K/V buffer,
// synchronous staged loads with tf32 cvt + permuted layouts:
//   Qs[m][pk32(d)]   stride 68   (A operand of S)
//   Ks[key][pk32(d)] stride 68   (B operand of S)
//   Vt[d][pk32(key)] stride 68   (B operand of PV, stored transposed)
// pk32(x) = (x/32)*32 + (x%4)*8 + (x%32)/4. All frag loads are LDS.64.
// ---------------------------------------------------------------------------
#define AS 68
#define ATT_Q_W   (128 * AS)    // 8704
#define ATT_K_W   (64 * AS)     // 4352
#define ATT_V_W   (64 * AS)     // 4352
#define ATT_SMEM_BYTES ((ATT_Q_W + ATT_K_W + ATT_V_W) * 4)   // 69632

__global__ __launch_bounds__(128)
void attn_tc()
{
    unsigned* Qs = dynsm_u;
    unsigned* Ks = Qs + ATT_Q_W;
    unsigned* Vt = Ks + ATT_K_W;

    const int tid  = threadIdx.x;
    const int lane = tid & 31;
    const int w    = tid >> 5;
    const int gid  = lane >> 2;
    const int tig  = lane & 3;
    const int qt   = blockIdx.x;
    const int bh   = blockIdx.y;
    const int b    = bh >> 4;
    const int h    = bh & 15;

    const float* base = g_qkv + (size_t)b * TT * N3;
    const float qscale = 0.125f * 1.44269504f;   // 1/sqrt(64) * log2(e)

    // Stage Q tile (128 x 64), scaled, tf32, permuted. d-chunk c, element c+i:
    // pk32(c+i) = (c/32)*32 + i*8 + (c%32)/4  (c % 4 == 0)
    #pragma unroll
    for (int r = 0; r < 16; r++) {
        int idx = tid + r * 128;
        int row = idx >> 4;
        int c   = (idx & 15) * 4;
        float4 v = *(const float4*)(base + (size_t)(qt * 128 + row) * N3 + h * HD + c);
        unsigned* p = Qs + row * AS + (c >> 5) * 32 + ((c & 31) >> 2);
        p[0]  = f2tf32(v.x * qscale);
        p[8]  = f2tf32(v.y * qscale);
        p[16] = f2tf32(v.z * qscale);
        p[24] = f2tf32(v.w * qscale);
    }

    float o[2][8][4];
    #pragma unroll
    for (int mi = 0; mi < 2; mi++)
        #pragma unroll
        for (int nj = 0; nj < 8; nj++)
            #pragma unroll
            for (int e = 0; e < 4; e++) o[mi][nj][e] = 0.0f;
    float mst[4] = {-1e30f, -1e30f, -1e30f, -1e30f};
    float lst[4] = {0.f, 0.f, 0.f, 0.f};

    const int ntiles = 2 * qt + 2;
    const int vkey = tid & 63;            // V staging: fixed key per thread
    const int vdh  = (tid >> 6) * 4;      // d base offset
    const int vpk  = (vkey >> 5) * 32 + (vkey & 3) * 8 + ((vkey & 31) >> 2);

    for (int kt = 0; kt < ntiles; kt++) {
        __syncthreads();   // all warps done with previous K/V

        // Stage K (coalesced rows, permuted d)
        const float* kb_ = base + (size_t)(kt * 64) * N3 + CC + h * HD;
        #pragma unroll
        for (int r = 0; r < 8; r++) {
            int idx = tid + r * 128;
            int row = idx >> 4;
            int c   = (idx & 15) * 4;
            float4 v = *(const float4*)(kb_ + (size_t)row * N3 + c);
            unsigned* p = Ks + row * AS + (c >> 5) * 32 + ((c & 31) >> 2);
            p[0]  = f2tf32(v.x);
            p[8]  = f2tf32(v.y);
            p[16] = f2tf32(v.z);
            p[24] = f2tf32(v.w);
        }
        // Stage V transposed: thread owns one key row, strided d chunks
        const float* vb_ = base + (size_t)(kt * 64) * N3 + 2 * CC + h * HD
                         + (size_t)vkey * N3 + vdh;
        #pragma unroll
        for (int r = 0; r < 8; r++) {
            float4 v = *(const float4*)(vb_ + r * 8);
            int d = vdh + r * 8;
            Vt[(d + 0) * AS + vpk] = f2tf32(v.x);
            Vt[(d + 1) * AS + vpk] = f2tf32(v.y);
            Vt[(d + 2) * AS + vpk] = f2tf32(v.z);
            Vt[(d + 3) * AS + vpk] = f2tf32(v.w);
        }
        __syncthreads();

        // --- S = Q @ K^T (in log2 domain) ---
        float s[2][8][4];
        #pragma unroll
        for (int mi = 0; mi < 2; mi++)
            #pragma unroll
            for (int nj = 0; nj < 8; nj++)
                #pragma unroll
                for (int e = 0; e < 4; e++) s[mi][nj][e] = 0.0f;

        #pragma unroll
        for (int ks = 0; ks < 8; ks++) {
            const int off = (ks >> 2) * 32 + tig * 8 + 2 * (ks & 3);
            uint2 qa[2][2];
            #pragma unroll
            for (int mi = 0; mi < 2; mi++) {
                int m = w * 32 + mi * 16 + gid;
                qa[mi][0] = *(const uint2*)&Qs[m * AS + off];
                qa[mi][1] = *(const uint2*)&Qs[(m + 8) * AS + off];
            }
            #pragma unroll
            for (int nj = 0; nj < 8; nj++) {
                uint2 qb = *(const uint2*)&Ks[(nj * 8 + gid) * AS + off];
                unsigned bfr[2] = {qb.x, qb.y};
                #pragma unroll
                for (int mi = 0; mi < 2; mi++) {
                    unsigned afr[4] = {qa[mi][0].x, qa[mi][1].x, qa[mi][0].y, qa[mi][1].y};
                    mma_tf32(s[mi][nj], afr, bfr);
                }
            }
        }

        // --- causal mask (only the two diagonal tiles) ---
        if (kt >= 2 * qt) {
            int colbase = kt * 64 + 2 * tig;
            int rowbase = qt * 128 + w * 32 + gid;
            #pragma unroll
            for (int mi = 0; mi < 2; mi++)
                #pragma unroll
                for (int nj = 0; nj < 8; nj++)
                    #pragma unroll
                    for (int e = 0; e < 4; e++) {
                        int row = rowbase + mi * 16 + ((e >> 1) << 3);
                        int col = colbase + nj * 8 + (e & 1);
                        if (col > row) s[mi][nj][e] = -1e30f;
                    }
        }

        // --- online softmax update (base-2) ---
        #pragma unroll
        for (int st = 0; st < 4; st++) {
            const int mi = st >> 1, hf = st & 1;
            float rm = -1e30f;
            #pragma unroll
            for (int nj = 0; nj < 8; nj++) {
                rm = fmaxf(rm, s[mi][nj][hf * 2]);
                rm = fmaxf(rm, s[mi][nj][hf * 2 + 1]);
            }
            rm = fmaxf(rm, __shfl_xor_sync(0xffffffff, rm, 1));
            rm = fmaxf(rm, __shfl_xor_sync(0xffffffff, rm, 2));
            float mnew = fmaxf(mst[st], rm);
            float alpha = ex2f(mst[st] - mnew);
            mst[st] = mnew;
            lst[st] *= alpha;
            #pragma unroll
            for (int nj = 0; nj < 8; nj++) {
                o[mi][nj][hf * 2]     *= alpha;
                o[mi][nj][hf * 2 + 1] *= alpha;
            }
            float psum = 0.0f;
            #pragma unroll
            for (int nj = 0; nj < 8; nj++) {
                float p0 = ex2f(s[mi][nj][hf * 2]     - mnew);
                float p1 = ex2f(s[mi][nj][hf * 2 + 1] - mnew);
                s[mi][nj][hf * 2]     = p0;
                s[mi][nj][hf * 2 + 1] = p1;
                psum += p0 + p1;
            }
            psum += __shfl_xor_sync(0xffffffff, psum, 1);
            psum += __shfl_xor_sync(0xffffffff, psum, 2);
            lst[st] += psum;
        }

        // --- O += P @ V ---
        const int src0 = (lane & ~3) | (tig >> 1);
        const int src1 = src0 + 2;
        const bool odd = tig & 1;
        #pragma unroll
        for (int kc = 0; kc < 8; kc++) {
            unsigned pa[2][4];
            #pragma unroll
            for (int mi = 0; mi < 2; mi++) {
                float c0 = s[mi][kc][0], c1 = s[mi][kc][1];
                float c2 = s[mi][kc][2], c3 = s[mi][kc][3];
                float v00 = __shfl_sync(0xffffffff, c0, src0);
                float v01 = __shfl_sync(0xffffffff, c1, src0);
                float v10 = __shfl_sync(0xffffffff, c0, src1);
                float v11 = __shfl_sync(0xffffffff, c1, src1);
                float v20 = __shfl_sync(0xffffffff, c2, src0);
                float v21 = __shfl_sync(0xffffffff, c3, src0);
                float v30 = __shfl_sync(0xffffffff, c2, src1);
                float v31 = __shfl_sync(0xffffffff, c3, src1);
                pa[mi][0] = __float_as_uint(odd ? v01 : v00);
                pa[mi][2] = __float_as_uint(odd ? v11 : v10);
                pa[mi][1] = __float_as_uint(odd ? v21 : v20);
                pa[mi][3] = __float_as_uint(odd ? v31 : v30);
            }
            const int off = (kc >> 2) * 32 + tig * 8 + 2 * (kc & 3);
            #pragma unroll
            for (int hj = 0; hj < 8; hj++) {
                uint2 qb = *(const uint2*)&Vt[(hj * 8 + gid) * AS + off];
                unsigned bfr[2] = {qb.x, qb.y};
                mma_tf32(o[0][hj], pa[0], bfr);
                mma_tf32(o[1][hj], pa[1], bfr);
            }
        }
    }

    // --- normalize + write [B,T,C] ---
    #pragma unroll
    for (int mi = 0; mi < 2; mi++) {
        float inv0 = 1.0f / lst[2 * mi];
        float inv1 = 1.0f / lst[2 * mi + 1];
        #pragma unroll
        for (int nj = 0; nj < 8; nj++) {
            int row = qt * 128 + w * 32 + mi * 16 + gid;
            int col = nj * 8 + 2 * tig;
            float* op = g_attn + (size_t)(b * TT + row) * CC + h * HD + col;
            *(float2*)op = make_float2(o[mi][nj][0] * inv0, o[mi][nj][1] * inv0);
            *(float2*)(op + (size_t)8 * CC) =
                make_float2(o[mi][nj][2] * inv1, o[mi][nj][3] * inv1);
        }
    }
}

// ---------------------------------------------------------------------------
// Launch
// ---------------------------------------------------------------------------
extern "C" void kernel_launch(void* const* d_in, const int* in_sizes, int n_in,
                              void* d_out, int out_size)
{
    const float* x     = (const float*)d_in[0];   // [B,T,C]
    const float* w_qkv = (const float*)d_in[1];   // [C,3C]
    const float* w_out = (const float*)d_in[2];   // [C,C]
    float* out = (float*)d_out;                   // [B,T,C]

    float* qkv_ptr = nullptr;
    float* attn_ptr = nullptr;
    cudaGetSymbolAddress((void**)&qkv_ptr, g_qkv);
    cudaGetSymbolAddress((void**)&attn_ptr, g_attn);

    cudaFuncSetAttribute(gemm_tf32, cudaFuncAttributeMaxDynamicSharedMemorySize,
                         GEMM_SMEM_BYTES);
    cudaFuncSetAttribute(attn_tc, cudaFuncAttributeMaxDynamicSharedMemorySize,
                         ATT_SMEM_BYTES);

    // 1) QKV projection: [8192,1024] @ [1024,3072]
    {
        dim3 grid(N3 / 128, M_ROWS / 256);
        gemm_tf32<<<grid, 256, GEMM_SMEM_BYTES>>>(x, w_qkv, qkv_ptr, M_ROWS, N3, CC);
    }
    // 2) Flash attention (tensor cores)
    {
        dim3 grid(TT / 128, BB * HH);
        attn_tc<<<grid, 128, ATT_SMEM_BYTES>>>();
    }
    // 3) Output projection: [8192,1024] @ [1024,1024]
    {
        dim3 grid(CC / 128, M_ROWS / 256);
        gemm_tf32<<<grid, 256, GEMM_SMEM_BYTES>>>(attn_ptr, w_out, out, M_ROWS, CC, CC);
    }
}

// round 6
// speedup vs baseline: 1.3721x; 1.3721x over previous
#include <cuda_runtime.h>
#include <math.h>

// Problem constants
#define BB 4
#define TT 2048
#define CC 1024
#define HH 16
#define HD 64
#define M_ROWS (BB * TT)       // 8192
#define N3 (3 * CC)            // 3072

// Scratch (device globals -- allocation API is forbidden)
__device__ float g_qkv[(size_t)M_ROWS * N3];     // 100.7 MB
__device__ float g_attn[(size_t)M_ROWS * CC];    // 33.6 MB

// ---------------------------------------------------------------------------
// Helpers
// ---------------------------------------------------------------------------
__device__ __forceinline__ unsigned f2tf32(float x) {
    unsigned r;
    asm("cvt.rna.tf32.f32 %0, %1;" : "=r"(r) : "f"(x));
    return r;
}
__device__ __forceinline__ float ex2f(float x) {
    float r;
    asm("ex2.approx.ftz.f32 %0, %1;" : "=f"(r) : "f"(x));
    return r;
}
__device__ __forceinline__ void mma_tf32(float* d, const unsigned* a, const unsigned* b) {
    asm volatile(
        "mma.sync.aligned.m16n8k8.row.col.f32.tf32.tf32.f32 "
        "{%0,%1,%2,%3}, {%4,%5,%6,%7}, {%8,%9}, {%0,%1,%2,%3};"
        : "+f"(d[0]), "+f"(d[1]), "+f"(d[2]), "+f"(d[3])
        : "r"(a[0]), "r"(a[1]), "r"(a[2]), "r"(a[3]), "r"(b[0]), "r"(b[1]));
}
__device__ __forceinline__ void cpasync16(void* smem, const void* gmem) {
    unsigned saddr = (unsigned)__cvta_generic_to_shared(smem);
    asm volatile("cp.async.cg.shared.global [%0], [%1], 16;" :: "r"(saddr), "l"(gmem));
}
__device__ __forceinline__ void cp_commit() {
    asm volatile("cp.async.commit_group;");
}
template <int N>
__device__ __forceinline__ void cp_wait() {
    asm volatile("cp.async.wait_group %0;" :: "n"(N));
}

extern __shared__ float dynsm[];

// ---------------------------------------------------------------------------
// tf32 tensor GEMM, 3-stage cp.async pipeline, FORCED 2 CTAs/SM.
// C[M,N] = A[M,K] @ B[K,N], row-major. M%128==0, N%128==0, K%32==0.
// 256 threads, 8 warps 2(M)x4(N); warp tile 64x32. Smem holds raw fp32;
// tf32 conversion (rna) at fragment load.
// ---------------------------------------------------------------------------
#define GAS 36     // As row stride (floats), pad 4 -> conflict-free frags
#define GBS 136    // Bs row stride, pad 8
#define GSTAGES 3
#define GSTAGE_F (128 * GAS + 32 * GBS)            // 8960 floats
#define GEMM_SMEM_BYTES (GSTAGES * GSTAGE_F * 4)   // 107520

__global__ __launch_bounds__(256, 2)
void gemm_tf32(const float* __restrict__ A, const float* __restrict__ B,
               float* __restrict__ C, int M, int N, int K)
{
    const int tid  = threadIdx.x;
    const int lane = tid & 31;
    const int wid  = tid >> 5;
    const int gid  = lane >> 2;
    const int tig  = lane & 3;
    const int wm   = wid >> 2;     // 0..1
    const int wn   = wid & 3;      // 0..3
    const int bM   = blockIdx.y * 128;
    const int bN   = blockIdx.x * 128;

    auto load_stage = [&](int s, int kb) {
        float* As = dynsm + s * GSTAGE_F;
        float* Bs = As + 128 * GAS;
        #pragma unroll
        for (int r = 0; r < 4; r++) {
            int idx = tid + r * 256;
            int row = idx >> 3;
            int c   = (idx & 7) * 4;
            cpasync16(&As[row * GAS + c], A + (size_t)(bM + row) * K + kb + c);
        }
        #pragma unroll
        for (int r = 0; r < 4; r++) {
            int idx = tid + r * 256;
            int row = idx >> 5;
            int c   = (idx & 31) * 4;
            cpasync16(&Bs[row * GBS + c], B + (size_t)(kb + row) * N + bN + c);
        }
    };

    const int ntile = K >> 5;
    #pragma unroll
    for (int s = 0; s < GSTAGES - 1; s++) {
        if (s < ntile) load_stage(s, s * 32);
        cp_commit();
    }

    float acc[4][4][4];
    #pragma unroll
    for (int mi = 0; mi < 4; mi++)
        #pragma unroll
        for (int nj = 0; nj < 4; nj++)
            #pragma unroll
            for (int e = 0; e < 4; e++) acc[mi][nj][e] = 0.0f;

    for (int i = 0; i < ntile; i++) {
        cp_wait<GSTAGES - 2>();
        __syncthreads();

        int nt = i + GSTAGES - 1;
        if (nt < ntile) load_stage(nt % GSTAGES, nt * 32);
        cp_commit();

        const float* As = dynsm + (i % GSTAGES) * GSTAGE_F;
        const float* Bs = As + 128 * GAS;

        #pragma unroll
        for (int ks = 0; ks < 4; ks++) {
            unsigned af[4][4], bf[4][2];
            #pragma unroll
            for (int mi = 0; mi < 4; mi++) {
                int m = wm * 64 + mi * 16 + gid;
                int k = ks * 8 + tig;
                af[mi][0] = f2tf32(As[m * GAS + k]);
                af[mi][1] = f2tf32(As[(m + 8) * GAS + k]);
                af[mi][2] = f2tf32(As[m * GAS + k + 4]);
                af[mi][3] = f2tf32(As[(m + 8) * GAS + k + 4]);
            }
            #pragma unroll
            for (int nj = 0; nj < 4; nj++) {
                int n = wn * 32 + nj * 8 + gid;
                int k = ks * 8 + tig;
                bf[nj][0] = f2tf32(Bs[k * GBS + n]);
                bf[nj][1] = f2tf32(Bs[(k + 4) * GBS + n]);
            }
            #pragma unroll
            for (int mi = 0; mi < 4; mi++)
                #pragma unroll
                for (int nj = 0; nj < 4; nj++)
                    mma_tf32(acc[mi][nj], af[mi], bf[nj]);
        }
    }

    // Epilogue
    #pragma unroll
    for (int mi = 0; mi < 4; mi++) {
        #pragma unroll
        for (int nj = 0; nj < 4; nj++) {
            int row = bM + wm * 64 + mi * 16 + gid;
            int col = bN + wn * 32 + nj * 8 + 2 * tig;
            float2 lo = make_float2(acc[mi][nj][0], acc[mi][nj][1]);
            float2 hi = make_float2(acc[mi][nj][2], acc[mi][nj][3]);
            *(float2*)(C + (size_t)row * N + col) = lo;
            *(float2*)(C + (size_t)(row + 8) * N + col) = hi;
        }
    }
}

// ---------------------------------------------------------------------------
// Tensor-core flash attention (causal, tf32 mma, fp32 accum). R2 version.
// CTA: 128 query rows, 4 warps x 32 rows (2 m16 tiles each). 64-key tiles.
// Online softmax in base-2 domain (scale*log2e folded into Q).
// grid: (T/128, B*H), block 128, dynamic smem 70656 B.
// ---------------------------------------------------------------------------
#define QS 68    // Q smem stride (pad 4): frag loads conflict-free
#define KSS 68   // K smem stride
#define VSS 72   // V smem stride (pad 8): B-frag loads conflict-free
#define ATT_SMEM_FLOATS (128 * QS + 64 * KSS + 64 * VSS)   // 17664
#define ATT_SMEM_BYTES  (ATT_SMEM_FLOATS * 4)              // 70656

__global__ __launch_bounds__(128)
void attn_tc()
{
    unsigned* Qs  = (unsigned*)dynsm;
    unsigned* Ksm = (unsigned*)dynsm + 128 * QS;
    unsigned* Vsm = Ksm + 64 * KSS;

    const int tid  = threadIdx.x;
    const int lane = tid & 31;
    const int w    = tid >> 5;
    const int gid  = lane >> 2;
    const int tig  = lane & 3;
    const int qt   = blockIdx.x;
    const int bh   = blockIdx.y;
    const int b    = bh >> 4;
    const int h    = bh & 15;

    const float* base = g_qkv + (size_t)b * TT * N3;
    const float qscale = 0.125f * 1.44269504f;   // 1/sqrt(64) * log2(e)

    // Load Q tile (128 x 64), scaled, tf32
    #pragma unroll
    for (int r = 0; r < 16; r++) {
        int idx = tid + r * 128;
        int row = idx >> 4;
        int c   = (idx & 15) * 4;
        float4 v = *(const float4*)(base + (size_t)(qt * 128 + row) * N3 + h * HD + c);
        uint4 t = make_uint4(f2tf32(v.x * qscale), f2tf32(v.y * qscale),
                             f2tf32(v.z * qscale), f2tf32(v.w * qscale));
        *(uint4*)&Qs[row * QS + c] = t;
    }

    float o[2][8][4];
    #pragma unroll
    for (int mi = 0; mi < 2; mi++)
        #pragma unroll
        for (int nj = 0; nj < 8; nj++)
            #pragma unroll
            for (int e = 0; e < 4; e++) o[mi][nj][e] = 0.0f;
    float mst[4] = {-1e30f, -1e30f, -1e30f, -1e30f};
    float lst[4] = {0.f, 0.f, 0.f, 0.f};

    const int ntiles = 2 * qt + 2;

    for (int kt = 0; kt < ntiles; kt++) {
        __syncthreads();   // previous iter's reads done before overwrite
        const float* kb_ = base + (size_t)(kt * 64) * N3 + CC + h * HD;
        const float* vb_ = base + (size_t)(kt * 64) * N3 + 2 * CC + h * HD;
        #pragma unroll
        for (int r = 0; r < 8; r++) {
            int idx = tid + r * 128;
            int row = idx >> 4;
            int c   = (idx & 15) * 4;
            float4 kv = *(const float4*)(kb_ + (size_t)row * N3 + c);
            float4 vv = *(const float4*)(vb_ + (size_t)row * N3 + c);
            *(uint4*)&Ksm[row * KSS + c] =
                make_uint4(f2tf32(kv.x), f2tf32(kv.y), f2tf32(kv.z), f2tf32(kv.w));
            *(uint4*)&Vsm[row * VSS + c] =
                make_uint4(f2tf32(vv.x), f2tf32(vv.y), f2tf32(vv.z), f2tf32(vv.w));
        }
        __syncthreads();

        // --- S = Q @ K^T (in log2 domain) ---
        float s[2][8][4];
        #pragma unroll
        for (int mi = 0; mi < 2; mi++)
            #pragma unroll
            for (int nj = 0; nj < 8; nj++)
                #pragma unroll
                for (int e = 0; e < 4; e++) s[mi][nj][e] = 0.0f;

        #pragma unroll
        for (int ks = 0; ks < 8; ks++) {
            unsigned a[2][4];
            #pragma unroll
            for (int mi = 0; mi < 2; mi++) {
                int m = w * 32 + mi * 16 + gid;
                int k = ks * 8 + tig;
                a[mi][0] = Qs[m * QS + k];
                a[mi][1] = Qs[(m + 8) * QS + k];
                a[mi][2] = Qs[m * QS + k + 4];
                a[mi][3] = Qs[(m + 8) * QS + k + 4];
            }
            #pragma unroll
            for (int nj = 0; nj < 8; nj++) {
                unsigned bf[2];
                int krow = nj * 8 + gid;
                bf[0] = Ksm[krow * KSS + ks * 8 + tig];
                bf[1] = Ksm[krow * KSS + ks * 8 + tig + 4];
                mma_tf32(s[0][nj], a[0], bf);
                mma_tf32(s[1][nj], a[1], bf);
            }
        }

        // --- causal mask (only the two diagonal tiles need it) ---
        if (kt >= 2 * qt) {
            int colbase = kt * 64 + 2 * tig;
            int rowbase = qt * 128 + w * 32 + gid;
            #pragma unroll
            for (int mi = 0; mi < 2; mi++)
                #pragma unroll
                for (int nj = 0; nj < 8; nj++)
                    #pragma unroll
                    for (int e = 0; e < 4; e++) {
                        int row = rowbase + mi * 16 + ((e >> 1) << 3);
                        int col = colbase + nj * 8 + (e & 1);
                        if (col > row) s[mi][nj][e] = -1e30f;
                    }
        }

        // --- online softmax update (base-2) ---
        #pragma unroll
        for (int st = 0; st < 4; st++) {
            const int mi = st >> 1, hf = st & 1;
            float rm = -1e30f;
            #pragma unroll
            for (int nj = 0; nj < 8; nj++) {
                rm = fmaxf(rm, s[mi][nj][hf * 2]);
                rm = fmaxf(rm, s[mi][nj][hf * 2 + 1]);
            }
            rm = fmaxf(rm, __shfl_xor_sync(0xffffffff, rm, 1));
            rm = fmaxf(rm, __shfl_xor_sync(0xffffffff, rm, 2));
            float mnew = fmaxf(mst[st], rm);
            float alpha = ex2f(mst[st] - mnew);
            mst[st] = mnew;
            lst[st] *= alpha;
            #pragma unroll
            for (int nj = 0; nj < 8; nj++) {
                o[mi][nj][hf * 2]     *= alpha;
                o[mi][nj][hf * 2 + 1] *= alpha;
            }
            float psum = 0.0f;
            #pragma unroll
            for (int nj = 0; nj < 8; nj++) {
                float p0 = ex2f(s[mi][nj][hf * 2]     - mnew);
                float p1 = ex2f(s[mi][nj][hf * 2 + 1] - mnew);
                s[mi][nj][hf * 2]     = p0;
                s[mi][nj][hf * 2 + 1] = p1;
                psum += p0 + p1;
            }
            psum += __shfl_xor_sync(0xffffffff, psum, 1);
            psum += __shfl_xor_sync(0xffffffff, psum, 2);
            lst[st] += psum;
        }

        // --- O += P @ V ---
        const int src0 = (lane & ~3) | (tig >> 1);
        const int src1 = src0 + 2;
        const bool odd = tig & 1;
        #pragma unroll
        for (int kc = 0; kc < 8; kc++) {
            unsigned pa[2][4];
            #pragma unroll
            for (int mi = 0; mi < 2; mi++) {
                float c0 = s[mi][kc][0], c1 = s[mi][kc][1];
                float c2 = s[mi][kc][2], c3 = s[mi][kc][3];
                float v00 = __shfl_sync(0xffffffff, c0, src0);
                float v01 = __shfl_sync(0xffffffff, c1, src0);
                float v10 = __shfl_sync(0xffffffff, c0, src1);
                float v11 = __shfl_sync(0xffffffff, c1, src1);
                float v20 = __shfl_sync(0xffffffff, c2, src0);
                float v21 = __shfl_sync(0xffffffff, c3, src0);
                float v30 = __shfl_sync(0xffffffff, c2, src1);
                float v31 = __shfl_sync(0xffffffff, c3, src1);
                pa[mi][0] = __float_as_uint(odd ? v01 : v00);
                pa[mi][2] = __float_as_uint(odd ? v11 : v10);
                pa[mi][1] = __float_as_uint(odd ? v21 : v20);
                pa[mi][3] = __float_as_uint(odd ? v31 : v30);
            }
            #pragma unroll
            for (int hj = 0; hj < 8; hj++) {
                unsigned bf[2];
                bf[0] = Vsm[(kc * 8 + tig) * VSS + hj * 8 + gid];
                bf[1] = Vsm[(kc * 8 + tig + 4) * VSS + hj * 8 + gid];
                mma_tf32(o[0][hj], pa[0], bf);
                mma_tf32(o[1][hj], pa[1], bf);
            }
        }
    }

    // --- normalize + write [B,T,C] ---
    #pragma unroll
    for (int mi = 0; mi < 2; mi++) {
        float inv0 = 1.0f / lst[2 * mi];
        float inv1 = 1.0f / lst[2 * mi + 1];
        #pragma unroll
        for (int nj = 0; nj < 8; nj++) {
            int row = qt * 128 + w * 32 + mi * 16 + gid;
            int col = nj * 8 + 2 * tig;
            float* op = g_attn + (size_t)(b * TT + row) * CC + h * HD + col;
            *(float2*)op = make_float2(o[mi][nj][0] * inv0, o[mi][nj][1] * inv0);
            *(float2*)(op + (size_t)8 * CC) =
                make_float2(o[mi][nj][2] * inv1, o[mi][nj][3] * inv1);
        }
    }
}

// ---------------------------------------------------------------------------
// Launch
// ---------------------------------------------------------------------------
extern "C" void kernel_launch(void* const* d_in, const int* in_sizes, int n_in,
                              void* d_out, int out_size)
{
    const float* x     = (const float*)d_in[0];   // [B,T,C]
    const float* w_qkv = (const float*)d_in[1];   // [C,3C]
    const float* w_out = (const float*)d_in[2];   // [C,C]
    float* out = (float*)d_out;                   // [B,T,C]

    float* qkv_ptr = nullptr;
    float* attn_ptr = nullptr;
    cudaGetSymbolAddress((void**)&qkv_ptr, g_qkv);
    cudaGetSymbolAddress((void**)&attn_ptr, g_attn);

    cudaFuncSetAttribute(gemm_tf32, cudaFuncAttributeMaxDynamicSharedMemorySize,
                         GEMM_SMEM_BYTES);
    cudaFuncSetAttribute(attn_tc, cudaFuncAttributeMaxDynamicSharedMemorySize,
                         ATT_SMEM_BYTES);

    // 1) QKV projection: [8192,1024] @ [1024,3072]
    {
        dim3 grid(N3 / 128, M_ROWS / 128);
        gemm_tf32<<<grid, 256, GEMM_SMEM_BYTES>>>(x, w_qkv, qkv_ptr, M_ROWS, N3, CC);
    }
    // 2) Flash attention (tensor cores)
    {
        dim3 grid(TT / 128, BB * HH);
        attn_tc<<<grid, 128, ATT_SMEM_BYTES>>>();
    }
    // 3) Output projection: [8192,1024] @ [1024,1024]
    {
        dim3 grid(CC / 128, M_ROWS / 128);
        gemm_tf32<<<grid, 256, GEMM_SMEM_BYTES>>>(attn_ptr, w_out, out, M_ROWS, CC, CC);
    }
}